// round 2
// baseline (speedup 1.0000x reference)
#include <cuda_runtime.h>

#define NEGINF (-1.0e30f)

// ---------------- persistent scratch ----------------
__device__ float g_h [1568 * 128];
__device__ float g_q [1568 * 128];
__device__ float g_k [1568 * 128];
__device__ float g_v [1568 * 128];
__device__ float g_pa[1568 * 128];   // attention partial (even j-blocks)
__device__ float g_pb[1568 * 128];   // attention partial (odd j-blocks)
__device__ float g_h1[1568 * 256];
__device__ float g_r [1568 * 128];   // raw ff2 output

// transposed weights [k][i]
__device__ float g_eWt [256 * 128];
__device__ float g_qkvWt[2 * 3 * 128 * 128];
__device__ float g_f1t [2 * 128 * 256];
__device__ float g_f2t [2 * 256 * 128];

// ---------------------------------------------------------------------------
// Weight transpose: grid (32, 11), 256 threads. dst[c*R + r] = src[r*C + c].
// ---------------------------------------------------------------------------
__global__ void wtrans_kernel(const float* eW,
                              const float* q0, const float* k0, const float* v0,
                              const float* f10, const float* f20,
                              const float* q1, const float* k1, const float* v1,
                              const float* f11, const float* f21) {
    __shared__ float tile[32][33];
    const int id = blockIdx.y;
    const float* src; float* dst; int R, C;
    switch (id) {
        case 0:  src = eW;  dst = g_eWt;               R = 128; C = 256; break;
        case 1:  src = q0;  dst = g_qkvWt + 0 * 16384; R = 128; C = 128; break;
        case 2:  src = k0;  dst = g_qkvWt + 1 * 16384; R = 128; C = 128; break;
        case 3:  src = v0;  dst = g_qkvWt + 2 * 16384; R = 128; C = 128; break;
        case 4:  src = f10; dst = g_f1t;               R = 256; C = 128; break;
        case 5:  src = f20; dst = g_f2t;               R = 128; C = 256; break;
        case 6:  src = q1;  dst = g_qkvWt + 3 * 16384; R = 128; C = 128; break;
        case 7:  src = k1;  dst = g_qkvWt + 4 * 16384; R = 128; C = 128; break;
        case 8:  src = v1;  dst = g_qkvWt + 5 * 16384; R = 128; C = 128; break;
        case 9:  src = f11; dst = g_f1t + 32768;       R = 256; C = 128; break;
        default: src = f21; dst = g_f2t + 32768;       R = 128; C = 256; break;
    }
    const int tilesC = C >> 5;
    const int lin = blockIdx.x;
    if (lin >= tilesC * (R >> 5)) return;
    const int tr = lin / tilesC, tc = lin % tilesC;
    const int x = threadIdx.x & 31, y = threadIdx.x >> 5;
#pragma unroll
    for (int s = 0; s < 4; s++)
        tile[y + s * 8][x] = src[(tr * 32 + y + s * 8) * C + tc * 32 + x];
    __syncthreads();
#pragma unroll
    for (int s = 0; s < 4; s++)
        dst[(tc * 32 + y + s * 8) * R + tr * 32 + x] = tile[x][y + s * 8];
}

// ---------------------------------------------------------------------------
// Embed: patchify + tropical GEMM (K=256) + pos.  grid (98, 2), 128 threads.
// BM=16, BN=64.  Full-K weight tile staged in smem, single barrier.
// ---------------------------------------------------------------------------
__global__ __launch_bounds__(128) void embed_kernel(const float* __restrict__ x,
                                                    const float* __restrict__ pos) {
    extern __shared__ float sm[];
    float* Xs = sm;            // [256][20]
    float* Ws = sm + 256 * 20; // [256][68]
    const int tid = threadIdx.x;
    const int r0 = blockIdx.x * 16;
    const int h0 = blockIdx.y * 64;

    // patchify load: 16 rows x 256 cols
#pragma unroll
    for (int t = 0; t < 32; t++) {
        int lin = t * 128 + tid;
        int px = lin & 15, m = (lin >> 4) & 15, py = lin >> 8;
        int r = r0 + m;
        int b = r / 196, n = r % 196;
        int gy = n / 14, gx = n % 14;
        Xs[(py * 16 + px) * 20 + m] =
            x[(b * 224 + gy * 16 + py) * 224 + gx * 16 + px];
    }
    // weight tile: 64 outs x 256 k (transposed, coalesced, conflict-free)
#pragma unroll
    for (int t = 0; t < 32; t++) {
        int idx = t * 128 + tid;
        int k = idx >> 4, i4 = idx & 15;
        *(float4*)(Ws + k * 68 + i4 * 4) =
            *(const float4*)(g_eWt + k * 128 + h0 + i4 * 4);
    }
    __syncthreads();

    const int ty = tid >> 4;   // 0..7 -> rows 2ty, 2ty+1
    const int tx = tid & 15;   // cols tx*4
    float acc[2][4];
#pragma unroll
    for (int m = 0; m < 2; m++)
#pragma unroll
        for (int n = 0; n < 4; n++) acc[m][n] = NEGINF;

#pragma unroll 8
    for (int k = 0; k < 256; k++) {
        float2 xf = *(const float2*)(Xs + k * 20 + ty * 2);
        float4 wf = *(const float4*)(Ws + k * 68 + tx * 4);
        float xv[2] = {xf.x, xf.y};
        float wv[4] = {wf.x, wf.y, wf.z, wf.w};
#pragma unroll
        for (int m = 0; m < 2; m++)
#pragma unroll
            for (int n = 0; n < 4; n++)
                acc[m][n] = fmaxf(acc[m][n], xv[m] + wv[n]);
    }
#pragma unroll
    for (int m = 0; m < 2; m++) {
        int r = r0 + ty * 2 + m;
        int nn = r % 196;
#pragma unroll
        for (int n = 0; n < 4; n++) {
            int col = h0 + tx * 4 + n;
            g_h[r * 128 + col] = acc[m][n] + pos[nn * 128 + col];
        }
    }
}

// ---------------------------------------------------------------------------
// QKV: pnorm(h) then tropical GEMM (K=128, N=128).  grid (98, 3), 128 thr.
// BM=16, full-K weight tile, single main barrier.
// ---------------------------------------------------------------------------
__global__ __launch_bounds__(128) void qkv_kernel(int layer) {
    extern __shared__ float sm[];
    float* Xs  = sm;                 // [128][20]
    float* Ws  = sm + 128 * 20;      // [128][132]
    float* red = Ws + 128 * 132;     // [16][8]
    float* rmx = red + 128;          // [16]
    const int tid = threadIdx.x;
    const int r0 = blockIdx.x * 16;
    const int which = blockIdx.y;

#pragma unroll
    for (int t = 0; t < 16; t++) {
        int lin = t * 128 + tid;
        int k = lin & 127, m = lin >> 7;
        Xs[k * 20 + m] = g_h[(r0 + m) * 128 + k];
    }
    const float* Wt = g_qkvWt + (layer * 3 + which) * 16384;
#pragma unroll
    for (int t = 0; t < 32; t++) {
        int idx = t * 128 + tid;
        int k = idx >> 5, i4 = idx & 31;
        *(float4*)(Ws + k * 132 + i4 * 4) =
            *(const float4*)(Wt + k * 128 + i4 * 4);
    }
    __syncthreads();
    // pnorm
    {
        int row = tid >> 3, sub = tid & 7;
        float mx = NEGINF;
        for (int k = sub; k < 128; k += 8) mx = fmaxf(mx, Xs[k * 20 + row]);
        red[row * 8 + sub] = mx;
    }
    __syncthreads();
    if (tid < 16) {
        float mx = red[tid * 8];
#pragma unroll
        for (int s = 1; s < 8; s++) mx = fmaxf(mx, red[tid * 8 + s]);
        rmx[tid] = mx;
    }
    __syncthreads();
#pragma unroll
    for (int t = 0; t < 16; t++) {
        int lin = t * 128 + tid;
        int k = lin & 127, m = lin >> 7;
        Xs[k * 20 + m] -= rmx[m];
    }
    __syncthreads();

    const int ty = tid >> 5, tx = tid & 31;
    float acc[4][4];
#pragma unroll
    for (int m = 0; m < 4; m++)
#pragma unroll
        for (int n = 0; n < 4; n++) acc[m][n] = NEGINF;

#pragma unroll 8
    for (int k = 0; k < 128; k++) {
        float4 xf = *(const float4*)(Xs + k * 20 + ty * 4);
        float4 wf = *(const float4*)(Ws + k * 132 + tx * 4);
        float xv[4] = {xf.x, xf.y, xf.z, xf.w};
        float wv[4] = {wf.x, wf.y, wf.z, wf.w};
#pragma unroll
        for (int m = 0; m < 4; m++)
#pragma unroll
            for (int n = 0; n < 4; n++)
                acc[m][n] = fmaxf(acc[m][n], xv[m] + wv[n]);
    }
    float* O = (which == 0) ? g_q : ((which == 1) ? g_k : g_v);
#pragma unroll
    for (int m = 0; m < 4; m++) {
        int r = r0 + ty * 4 + m;
        float4 v = make_float4(acc[m][0], acc[m][1], acc[m][2], acc[m][3]);
        *(float4*)(O + r * 128 + tx * 4) = v;
    }
}

// ---------------------------------------------------------------------------
// Attention partial.  grid (13, 8, 2): 16 q-rows, batch, j-parity.
// Writes raw O partial (no rowmax) to g_pa / g_pb.  128 threads.
// ---------------------------------------------------------------------------
__global__ __launch_bounds__(128) void attnP_kernel() {
    __shared__ float Qs[128 * 20];
    __shared__ float Ks[128 * 34];
    __shared__ float Vs[32 * 132];
    __shared__ float Ss[32 * 18];
    const int tid = threadIdx.x;
    const int b = blockIdx.y;
    const int i0 = blockIdx.x * 16;
    const int z = blockIdx.z;
    const int ty = tid >> 4, tx = tid & 15;

#pragma unroll
    for (int t = 0; t < 16; t++) {
        int lin = t * 128 + tid;
        int d = lin & 127, i = lin >> 7;
        Qs[d * 20 + i] = (i0 + i < 196) ? g_q[(b * 196 + i0 + i) * 128 + d] : NEGINF;
    }

    float o0[8], o1[8];
#pragma unroll
    for (int n = 0; n < 8; n++) { o0[n] = NEGINF; o1[n] = NEGINF; }

    for (int j0 = z * 32; j0 < 196; j0 += 64) {
        __syncthreads();
#pragma unroll
        for (int t = 0; t < 32; t++) {
            int lin = t * 128 + tid;
            int d = lin & 127, j = lin >> 7;
            bool ok = (j0 + j) < 196;
            int r = b * 196 + j0 + j;
            Ks[d * 34 + j] = ok ? g_k[r * 128 + d] : NEGINF;
            Vs[j * 132 + d] = ok ? g_v[r * 128 + d] : NEGINF;
        }
        __syncthreads();

        float s00 = NEGINF, s01 = NEGINF, s10 = NEGINF, s11 = NEGINF;
#pragma unroll 8
        for (int d = 0; d < 128; d++) {
            float2 qf = *(const float2*)(Qs + d * 20 + ty * 2);
            float2 kf = *(const float2*)(Ks + d * 34 + tx * 2);
            s00 = fmaxf(s00, qf.x + kf.x);
            s01 = fmaxf(s01, qf.x + kf.y);
            s10 = fmaxf(s10, qf.y + kf.x);
            s11 = fmaxf(s11, qf.y + kf.y);
        }
        Ss[(tx * 2 + 0) * 18 + ty * 2 + 0] = s00;
        Ss[(tx * 2 + 1) * 18 + ty * 2 + 0] = s01;
        Ss[(tx * 2 + 0) * 18 + ty * 2 + 1] = s10;
        Ss[(tx * 2 + 1) * 18 + ty * 2 + 1] = s11;
        __syncthreads();

#pragma unroll 8
        for (int j = 0; j < 32; j++) {
            float2 sf = *(const float2*)(Ss + j * 18 + ty * 2);
            float4 va = *(const float4*)(Vs + j * 132 + tx * 8);
            float4 vb = *(const float4*)(Vs + j * 132 + tx * 8 + 4);
            float vv[8] = {va.x, va.y, va.z, va.w, vb.x, vb.y, vb.z, vb.w};
#pragma unroll
            for (int n = 0; n < 8; n++) {
                o0[n] = fmaxf(o0[n], sf.x + vv[n]);
                o1[n] = fmaxf(o1[n], sf.y + vv[n]);
            }
        }
    }

    float* P = z ? g_pb : g_pa;
    int i_a = ty * 2, i_b = ty * 2 + 1;
    if (i0 + i_a < 196) {
        int base = (b * 196 + i0 + i_a) * 128 + tx * 8;
        *(float4*)(P + base)     = make_float4(o0[0], o0[1], o0[2], o0[3]);
        *(float4*)(P + base + 4) = make_float4(o0[4], o0[5], o0[6], o0[7]);
    }
    if (i0 + i_b < 196) {
        int base = (b * 196 + i0 + i_b) * 128 + tx * 8;
        *(float4*)(P + base)     = make_float4(o1[0], o1[1], o1[2], o1[3]);
        *(float4*)(P + base + 4) = make_float4(o1[4], o1[5], o1[6], o1[7]);
    }
}

// ---------------------------------------------------------------------------
// FF1 with fused attention combine + residual + pnorm.  grid (98, 2), 128 thr.
// a = max(pa,pb); h = max(h, a - rowmax(a)); write h (y==0); xn = pnorm(h);
// h1 = max(tropmm(xn, f1W_half), tau).
// ---------------------------------------------------------------------------
__global__ __launch_bounds__(128) void ff1_kernel(int layer, const float* __restrict__ tau) {
    extern __shared__ float sm[];
    float* Xs  = sm;                     // [128][20]
    float* As  = sm + 128 * 20;          // [128][20]
    float* Ws  = As + 128 * 20;          // [128][132]
    float* red = Ws + 128 * 132;         // [16][8]
    float* rmx = red + 128;              // [16]
    const int tid = threadIdx.x;
    const int r0 = blockIdx.x * 16;
    const int h0 = blockIdx.y * 128;

#pragma unroll
    for (int t = 0; t < 16; t++) {
        int lin = t * 128 + tid;
        int k = lin & 127, m = lin >> 7;
        int gi = (r0 + m) * 128 + k;
        Xs[k * 20 + m] = g_h[gi];
        As[k * 20 + m] = fmaxf(g_pa[gi], g_pb[gi]);
    }
    const float* Wt = g_f1t + layer * 32768;
#pragma unroll
    for (int t = 0; t < 32; t++) {
        int idx = t * 128 + tid;
        int k = idx >> 5, i4 = idx & 31;
        *(float4*)(Ws + k * 132 + i4 * 4) =
            *(const float4*)(Wt + k * 256 + h0 + i4 * 4);
    }
    __syncthreads();
    // rowmax(a)
    {
        int row = tid >> 3, sub = tid & 7;
        float mx = NEGINF;
        for (int k = sub; k < 128; k += 8) mx = fmaxf(mx, As[k * 20 + row]);
        red[row * 8 + sub] = mx;
    }
    __syncthreads();
    if (tid < 16) {
        float mx = red[tid * 8];
#pragma unroll
        for (int s = 1; s < 8; s++) mx = fmaxf(mx, red[tid * 8 + s]);
        rmx[tid] = mx;
    }
    __syncthreads();
    // h = max(h, a - rma); write back (y==0 only, idempotent value)
#pragma unroll
    for (int t = 0; t < 16; t++) {
        int lin = t * 128 + tid;
        int k = lin & 127, m = lin >> 7;
        float v = fmaxf(Xs[k * 20 + m], As[k * 20 + m] - rmx[m]);
        Xs[k * 20 + m] = v;
        if (blockIdx.y == 0) g_h[(r0 + m) * 128 + k] = v;
    }
    __syncthreads();
    // pnorm(h)
    {
        int row = tid >> 3, sub = tid & 7;
        float mx = NEGINF;
        for (int k = sub; k < 128; k += 8) mx = fmaxf(mx, Xs[k * 20 + row]);
        red[row * 8 + sub] = mx;
    }
    __syncthreads();
    if (tid < 16) {
        float mx = red[tid * 8];
#pragma unroll
        for (int s = 1; s < 8; s++) mx = fmaxf(mx, red[tid * 8 + s]);
        rmx[tid] = mx;
    }
    __syncthreads();
#pragma unroll
    for (int t = 0; t < 16; t++) {
        int lin = t * 128 + tid;
        int k = lin & 127, m = lin >> 7;
        Xs[k * 20 + m] -= rmx[m];
    }
    __syncthreads();

    const int ty = tid >> 5, tx = tid & 31;
    float acc[4][4];
#pragma unroll
    for (int m = 0; m < 4; m++)
#pragma unroll
        for (int n = 0; n < 4; n++) acc[m][n] = NEGINF;

#pragma unroll 8
    for (int k = 0; k < 128; k++) {
        float4 xf = *(const float4*)(Xs + k * 20 + ty * 4);
        float4 wf = *(const float4*)(Ws + k * 132 + tx * 4);
        float xv[4] = {xf.x, xf.y, xf.z, xf.w};
        float wv[4] = {wf.x, wf.y, wf.z, wf.w};
#pragma unroll
        for (int m = 0; m < 4; m++)
#pragma unroll
            for (int n = 0; n < 4; n++)
                acc[m][n] = fmaxf(acc[m][n], xv[m] + wv[n]);
    }
    float tv = tau[0];
#pragma unroll
    for (int m = 0; m < 4; m++) {
        int r = r0 + ty * 4 + m;
        float4 v = make_float4(fmaxf(acc[m][0], tv), fmaxf(acc[m][1], tv),
                               fmaxf(acc[m][2], tv), fmaxf(acc[m][3], tv));
        *(float4*)(g_h1 + r * 256 + h0 + tx * 4) = v;
    }
}

// ---------------------------------------------------------------------------
// FF2 GEMM (raw): K=256, BN=64.  grid (98, 2), 128 threads -> g_r.
// ---------------------------------------------------------------------------
__global__ __launch_bounds__(128) void ff2_kernel(int layer) {
    extern __shared__ float sm[];
    float* Xs = sm;            // [256][20]
    float* Ws = sm + 256 * 20; // [256][68]
    const int tid = threadIdx.x;
    const int r0 = blockIdx.x * 16;
    const int h0 = blockIdx.y * 64;

#pragma unroll
    for (int t = 0; t < 32; t++) {
        int lin = t * 128 + tid;
        int k = lin & 255, m = lin >> 8;
        Xs[k * 20 + m] = g_h1[(r0 + m) * 256 + k];
    }
    const float* Wt = g_f2t + layer * 32768;
#pragma unroll
    for (int t = 0; t < 32; t++) {
        int idx = t * 128 + tid;
        int k = idx >> 4, i4 = idx & 15;
        *(float4*)(Ws + k * 68 + i4 * 4) =
            *(const float4*)(Wt + k * 128 + h0 + i4 * 4);
    }
    __syncthreads();

    const int ty = tid >> 4, tx = tid & 15;
    float acc[2][4];
#pragma unroll
    for (int m = 0; m < 2; m++)
#pragma unroll
        for (int n = 0; n < 4; n++) acc[m][n] = NEGINF;

#pragma unroll 8
    for (int k = 0; k < 256; k++) {
        float2 xf = *(const float2*)(Xs + k * 20 + ty * 2);
        float4 wf = *(const float4*)(Ws + k * 68 + tx * 4);
        float xv[2] = {xf.x, xf.y};
        float wv[4] = {wf.x, wf.y, wf.z, wf.w};
#pragma unroll
        for (int m = 0; m < 2; m++)
#pragma unroll
            for (int n = 0; n < 4; n++)
                acc[m][n] = fmaxf(acc[m][n], xv[m] + wv[n]);
    }
#pragma unroll
    for (int m = 0; m < 2; m++) {
        int r = r0 + ty * 2 + m;
        float4 v = make_float4(acc[m][0], acc[m][1], acc[m][2], acc[m][3]);
        *(float4*)(g_r + r * 128 + h0 + tx * 4) = v;
    }
}

// ---------------------------------------------------------------------------
// FF2 combine: rowmax over 128 outs, h = max(h, r - rm).  grid 196, 256 thr.
// One warp per row.
// ---------------------------------------------------------------------------
__global__ void comb2_kernel() {
    const int w = threadIdx.x >> 5, lane = threadIdx.x & 31;
    const int r = blockIdx.x * 8 + w;
    float4 v = *(const float4*)(g_r + r * 128 + lane * 4);
    float m = fmaxf(fmaxf(v.x, v.y), fmaxf(v.z, v.w));
#pragma unroll
    for (int s = 16; s; s >>= 1) m = fmaxf(m, __shfl_xor_sync(0xffffffffu, m, s));
    float4 h = *(float4*)(g_h + r * 128 + lane * 4);
    h.x = fmaxf(h.x, v.x - m);
    h.y = fmaxf(h.y, v.y - m);
    h.z = fmaxf(h.z, v.z - m);
    h.w = fmaxf(h.w, v.w - m);
    *(float4*)(g_h + r * 128 + lane * 4) = h;
}

// ---------------------------------------------------------------------------
// Pool + head.  grid (8, 8), 128 threads.
// ---------------------------------------------------------------------------
__global__ void head_kernel(const float* __restrict__ hW,
                            const float* __restrict__ ls,
                            float* __restrict__ out) {
    __shared__ float pooled[128];
    const int b = blockIdx.x, ct = blockIdx.y, tid = threadIdx.x;

    const float* hp = g_h + (b * 196) * 128 + tid;
    float m0 = NEGINF, m1 = NEGINF, m2 = NEGINF, m3 = NEGINF;
#pragma unroll 4
    for (int n = 0; n < 196; n += 4) {
        m0 = fmaxf(m0, hp[(n + 0) * 128]);
        m1 = fmaxf(m1, hp[(n + 1) * 128]);
        m2 = fmaxf(m2, hp[(n + 2) * 128]);
        m3 = fmaxf(m3, hp[(n + 3) * 128]);
    }
    pooled[tid] = fmaxf(fmaxf(m0, m1), fmaxf(m2, m3));
    __syncthreads();

    int c = ct * 125 + tid;
    if (tid < 125) {
        const float* w = hW + c * 128;
        float a = NEGINF;
#pragma unroll 8
        for (int d = 0; d < 128; d++) a = fmaxf(a, pooled[d] + w[d]);
        out[b * 1000 + c] = a * ls[0];
    }
}

// ---------------------------------------------------------------------------
static const int SMEM_EMBED = (256 * 20 + 256 * 68) * 4;
static const int SMEM_QKV   = (128 * 20 + 128 * 132 + 128 + 16) * 4;
static const int SMEM_FF1   = (128 * 20 * 2 + 128 * 132 + 128 + 16) * 4;
static const int SMEM_FF2   = (256 * 20 + 256 * 68) * 4;

extern "C" void kernel_launch(void* const* d_in, const int* in_sizes, int n_in,
                              void* d_out, int out_size) {
    const float* x   = (const float*)d_in[0];
    const float* eW  = (const float*)d_in[1];
    const float* pos = (const float*)d_in[2];
    const float* qW[2]  = {(const float*)d_in[3],  (const float*)d_in[9]};
    const float* kW[2]  = {(const float*)d_in[4],  (const float*)d_in[10]};
    const float* vW[2]  = {(const float*)d_in[5],  (const float*)d_in[11]};
    const float* f1W[2] = {(const float*)d_in[6],  (const float*)d_in[12]};
    const float* f2W[2] = {(const float*)d_in[7],  (const float*)d_in[13]};
    const float* tau[2] = {(const float*)d_in[8],  (const float*)d_in[14]};
    const float* hW  = (const float*)d_in[15];
    const float* ls  = (const float*)d_in[16];
    float* out = (float*)d_out;

    cudaFuncSetAttribute(embed_kernel, cudaFuncAttributeMaxDynamicSharedMemorySize, SMEM_EMBED);
    cudaFuncSetAttribute(qkv_kernel,   cudaFuncAttributeMaxDynamicSharedMemorySize, SMEM_QKV);
    cudaFuncSetAttribute(ff1_kernel,   cudaFuncAttributeMaxDynamicSharedMemorySize, SMEM_FF1);
    cudaFuncSetAttribute(ff2_kernel,   cudaFuncAttributeMaxDynamicSharedMemorySize, SMEM_FF2);

    wtrans_kernel<<<dim3(32, 11), 256>>>(eW, qW[0], kW[0], vW[0], f1W[0], f2W[0],
                                         qW[1], kW[1], vW[1], f1W[1], f2W[1]);
    embed_kernel<<<dim3(98, 2), 128, SMEM_EMBED>>>(x, pos);
    for (int l = 0; l < 2; l++) {
        qkv_kernel<<<dim3(98, 3), 128, SMEM_QKV>>>(l);
        attnP_kernel<<<dim3(13, 8, 2), 128>>>();
        ff1_kernel<<<dim3(98, 2), 128, SMEM_FF1>>>(l, tau[l]);
        ff2_kernel<<<dim3(98, 2), 128, SMEM_FF2>>>(l);
        comb2_kernel<<<196, 256>>>();
    }
    head_kernel<<<dim3(8, 8), 128>>>(hW, ls, out);
}

// round 4
// speedup vs baseline: 1.5263x; 1.5263x over previous
#include <cuda_runtime.h>

#define NEGINF (-1.0e30f)

// ---------------- persistent scratch ----------------
__device__ float g_h [1568 * 128];
__device__ float g_q [1568 * 128];
__device__ float g_k [1568 * 128];
__device__ float g_v [1568 * 128];
__device__ float g_pa[1568 * 128];   // attention partial (even j-blocks)
__device__ float g_pb[1568 * 128];   // attention partial (odd j-blocks)
__device__ float g_h1[1568 * 256];
__device__ float g_r [1568 * 128];   // raw ff2 output

// transposed weights [k][i]
__device__ float g_eWt [256 * 128];
__device__ float g_qkvWt[2 * 3 * 128 * 128];
__device__ float g_f1t [2 * 128 * 256];
__device__ float g_f2t [2 * 256 * 128];

// ---------------------------------------------------------------------------
// Weight transpose: grid (32, 11), 256 threads. dst[c*R + r] = src[r*C + c].
// ---------------------------------------------------------------------------
__global__ void wtrans_kernel(const float* eW,
                              const float* q0, const float* k0, const float* v0,
                              const float* f10, const float* f20,
                              const float* q1, const float* k1, const float* v1,
                              const float* f11, const float* f21) {
    __shared__ float tile[32][33];
    const int id = blockIdx.y;
    const float* src; float* dst; int R, C;
    switch (id) {
        case 0:  src = eW;  dst = g_eWt;               R = 128; C = 256; break;
        case 1:  src = q0;  dst = g_qkvWt + 0 * 16384; R = 128; C = 128; break;
        case 2:  src = k0;  dst = g_qkvWt + 1 * 16384; R = 128; C = 128; break;
        case 3:  src = v0;  dst = g_qkvWt + 2 * 16384; R = 128; C = 128; break;
        case 4:  src = f10; dst = g_f1t;               R = 256; C = 128; break;
        case 5:  src = f20; dst = g_f2t;               R = 128; C = 256; break;
        case 6:  src = q1;  dst = g_qkvWt + 3 * 16384; R = 128; C = 128; break;
        case 7:  src = k1;  dst = g_qkvWt + 4 * 16384; R = 128; C = 128; break;
        case 8:  src = v1;  dst = g_qkvWt + 5 * 16384; R = 128; C = 128; break;
        case 9:  src = f11; dst = g_f1t + 32768;       R = 256; C = 128; break;
        default: src = f21; dst = g_f2t + 32768;       R = 128; C = 256; break;
    }
    const int tilesC = C >> 5;
    const int lin = blockIdx.x;
    if (lin >= tilesC * (R >> 5)) return;
    const int tr = lin / tilesC, tc = lin % tilesC;
    const int x = threadIdx.x & 31, y = threadIdx.x >> 5;
#pragma unroll
    for (int s = 0; s < 4; s++)
        tile[y + s * 8][x] = src[(tr * 32 + y + s * 8) * C + tc * 32 + x];
    __syncthreads();
#pragma unroll
    for (int s = 0; s < 4; s++)
        dst[(tc * 32 + y + s * 8) * R + tr * 32 + x] = tile[x][y + s * 8];
}

// ---------------------------------------------------------------------------
// Embed: patchify + tropical GEMM (K=256) + pos.  grid (98, 2), 128 threads.
// BM=16, BN=64.  Full-K weight tile staged in smem, single barrier.
// ---------------------------------------------------------------------------
__global__ __launch_bounds__(128) void embed_kernel(const float* __restrict__ x,
                                                    const float* __restrict__ pos) {
    extern __shared__ float sm[];
    float* Xs = sm;            // [256][20]
    float* Ws = sm + 256 * 20; // [256][68]
    const int tid = threadIdx.x;
    const int r0 = blockIdx.x * 16;
    const int h0 = blockIdx.y * 64;

    // patchify load: 16 rows x 256 cols
#pragma unroll
    for (int t = 0; t < 32; t++) {
        int lin = t * 128 + tid;
        int px = lin & 15, m = (lin >> 4) & 15, py = lin >> 8;
        int r = r0 + m;
        int b = r / 196, n = r % 196;
        int gy = n / 14, gx = n % 14;
        Xs[(py * 16 + px) * 20 + m] =
            x[(b * 224 + gy * 16 + py) * 224 + gx * 16 + px];
    }
    // weight tile: 64 outs x 256 k (transposed, coalesced, conflict-free)
#pragma unroll
    for (int t = 0; t < 32; t++) {
        int idx = t * 128 + tid;
        int k = idx >> 4, i4 = idx & 15;
        *(float4*)(Ws + k * 68 + i4 * 4) =
            *(const float4*)(g_eWt + k * 128 + h0 + i4 * 4);
    }
    __syncthreads();

    const int ty = tid >> 4;   // 0..7 -> rows 2ty, 2ty+1
    const int tx = tid & 15;   // cols tx*4
    float acc[2][4];
#pragma unroll
    for (int m = 0; m < 2; m++)
#pragma unroll
        for (int n = 0; n < 4; n++) acc[m][n] = NEGINF;

#pragma unroll 8
    for (int k = 0; k < 256; k++) {
        float2 xf = *(const float2*)(Xs + k * 20 + ty * 2);
        float4 wf = *(const float4*)(Ws + k * 68 + tx * 4);
        float xv[2] = {xf.x, xf.y};
        float wv[4] = {wf.x, wf.y, wf.z, wf.w};
#pragma unroll
        for (int m = 0; m < 2; m++)
#pragma unroll
            for (int n = 0; n < 4; n++)
                acc[m][n] = fmaxf(acc[m][n], xv[m] + wv[n]);
    }
#pragma unroll
    for (int m = 0; m < 2; m++) {
        int r = r0 + ty * 2 + m;
        int nn = r % 196;
#pragma unroll
        for (int n = 0; n < 4; n++) {
            int col = h0 + tx * 4 + n;
            g_h[r * 128 + col] = acc[m][n] + pos[nn * 128 + col];
        }
    }
}

// ---------------------------------------------------------------------------
// QKV: pnorm(h) then tropical GEMM (K=128, N=128).  grid (98, 3), 128 thr.
// BM=16, full-K weight tile, single main barrier.
// ---------------------------------------------------------------------------
__global__ __launch_bounds__(128) void qkv_kernel(int layer) {
    extern __shared__ float sm[];
    float* Xs  = sm;                 // [128][20]
    float* Ws  = sm + 128 * 20;      // [128][132]
    float* red = Ws + 128 * 132;     // [16][8]
    float* rmx = red + 128;          // [16]
    const int tid = threadIdx.x;
    const int r0 = blockIdx.x * 16;
    const int which = blockIdx.y;

#pragma unroll
    for (int t = 0; t < 16; t++) {
        int lin = t * 128 + tid;
        int k = lin & 127, m = lin >> 7;
        Xs[k * 20 + m] = g_h[(r0 + m) * 128 + k];
    }
    const float* Wt = g_qkvWt + (layer * 3 + which) * 16384;
#pragma unroll
    for (int t = 0; t < 32; t++) {
        int idx = t * 128 + tid;
        int k = idx >> 5, i4 = idx & 31;
        *(float4*)(Ws + k * 132 + i4 * 4) =
            *(const float4*)(Wt + k * 128 + i4 * 4);
    }
    __syncthreads();
    // pnorm
    {
        int row = tid >> 3, sub = tid & 7;
        float mx = NEGINF;
        for (int k = sub; k < 128; k += 8) mx = fmaxf(mx, Xs[k * 20 + row]);
        red[row * 8 + sub] = mx;
    }
    __syncthreads();
    if (tid < 16) {
        float mx = red[tid * 8];
#pragma unroll
        for (int s = 1; s < 8; s++) mx = fmaxf(mx, red[tid * 8 + s]);
        rmx[tid] = mx;
    }
    __syncthreads();
#pragma unroll
    for (int t = 0; t < 16; t++) {
        int lin = t * 128 + tid;
        int k = lin & 127, m = lin >> 7;
        Xs[k * 20 + m] -= rmx[m];
    }
    __syncthreads();

    const int ty = tid >> 5, tx = tid & 31;
    float acc[4][4];
#pragma unroll
    for (int m = 0; m < 4; m++)
#pragma unroll
        for (int n = 0; n < 4; n++) acc[m][n] = NEGINF;

#pragma unroll 8
    for (int k = 0; k < 128; k++) {
        float4 xf = *(const float4*)(Xs + k * 20 + ty * 4);
        float4 wf = *(const float4*)(Ws + k * 132 + tx * 4);
        float xv[4] = {xf.x, xf.y, xf.z, xf.w};
        float wv[4] = {wf.x, wf.y, wf.z, wf.w};
#pragma unroll
        for (int m = 0; m < 4; m++)
#pragma unroll
            for (int n = 0; n < 4; n++)
                acc[m][n] = fmaxf(acc[m][n], xv[m] + wv[n]);
    }
    float* O = (which == 0) ? g_q : ((which == 1) ? g_k : g_v);
#pragma unroll
    for (int m = 0; m < 4; m++) {
        int r = r0 + ty * 4 + m;
        float4 v = make_float4(acc[m][0], acc[m][1], acc[m][2], acc[m][3]);
        *(float4*)(O + r * 128 + tx * 4) = v;
    }
}

// ---------------------------------------------------------------------------
// Attention partial.  grid (13, 8, 2): 16 q-rows, batch, j-parity.
// Writes raw O partial (no rowmax) to g_pa / g_pb.  128 threads.
// ---------------------------------------------------------------------------
__global__ __launch_bounds__(128) void attnP_kernel() {
    __shared__ float Qs[128 * 20];
    __shared__ float Ks[128 * 34];
    __shared__ float Vs[32 * 132];
    __shared__ float Ss[32 * 18];
    const int tid = threadIdx.x;
    const int b = blockIdx.y;
    const int i0 = blockIdx.x * 16;
    const int z = blockIdx.z;
    const int ty = tid >> 4, tx = tid & 15;

#pragma unroll
    for (int t = 0; t < 16; t++) {
        int lin = t * 128 + tid;
        int d = lin & 127, i = lin >> 7;
        Qs[d * 20 + i] = (i0 + i < 196) ? g_q[(b * 196 + i0 + i) * 128 + d] : NEGINF;
    }

    float o0[8], o1[8];
#pragma unroll
    for (int n = 0; n < 8; n++) { o0[n] = NEGINF; o1[n] = NEGINF; }

    for (int j0 = z * 32; j0 < 196; j0 += 64) {
        __syncthreads();
#pragma unroll
        for (int t = 0; t < 32; t++) {
            int lin = t * 128 + tid;
            int d = lin & 127, j = lin >> 7;
            bool ok = (j0 + j) < 196;
            int r = b * 196 + j0 + j;
            Ks[d * 34 + j] = ok ? g_k[r * 128 + d] : NEGINF;
            Vs[j * 132 + d] = ok ? g_v[r * 128 + d] : NEGINF;
        }
        __syncthreads();

        float s00 = NEGINF, s01 = NEGINF, s10 = NEGINF, s11 = NEGINF;
#pragma unroll 8
        for (int d = 0; d < 128; d++) {
            float2 qf = *(const float2*)(Qs + d * 20 + ty * 2);
            float2 kf = *(const float2*)(Ks + d * 34 + tx * 2);
            s00 = fmaxf(s00, qf.x + kf.x);
            s01 = fmaxf(s01, qf.x + kf.y);
            s10 = fmaxf(s10, qf.y + kf.x);
            s11 = fmaxf(s11, qf.y + kf.y);
        }
        Ss[(tx * 2 + 0) * 18 + ty * 2 + 0] = s00;
        Ss[(tx * 2 + 1) * 18 + ty * 2 + 0] = s01;
        Ss[(tx * 2 + 0) * 18 + ty * 2 + 1] = s10;
        Ss[(tx * 2 + 1) * 18 + ty * 2 + 1] = s11;
        __syncthreads();

#pragma unroll 8
        for (int j = 0; j < 32; j++) {
            float2 sf = *(const float2*)(Ss + j * 18 + ty * 2);
            float4 va = *(const float4*)(Vs + j * 132 + tx * 8);
            float4 vb = *(const float4*)(Vs + j * 132 + tx * 8 + 4);
            float vv[8] = {va.x, va.y, va.z, va.w, vb.x, vb.y, vb.z, vb.w};
#pragma unroll
            for (int n = 0; n < 8; n++) {
                o0[n] = fmaxf(o0[n], sf.x + vv[n]);
                o1[n] = fmaxf(o1[n], sf.y + vv[n]);
            }
        }
    }

    float* P = z ? g_pb : g_pa;
    int i_a = ty * 2, i_b = ty * 2 + 1;
    if (i0 + i_a < 196) {
        int base = (b * 196 + i0 + i_a) * 128 + tx * 8;
        *(float4*)(P + base)     = make_float4(o0[0], o0[1], o0[2], o0[3]);
        *(float4*)(P + base + 4) = make_float4(o0[4], o0[5], o0[6], o0[7]);
    }
    if (i0 + i_b < 196) {
        int base = (b * 196 + i0 + i_b) * 128 + tx * 8;
        *(float4*)(P + base)     = make_float4(o1[0], o1[1], o1[2], o1[3]);
        *(float4*)(P + base + 4) = make_float4(o1[4], o1[5], o1[6], o1[7]);
    }
}

// ---------------------------------------------------------------------------
// FF1 with fused attention combine + residual + pnorm.  grid (98, 2), 128 thr.
// a = max(pa,pb); h = max(h, a - rowmax(a)); write h (y==0); xn = pnorm(h);
// h1 = max(tropmm(xn, f1W_half), tau).
// ---------------------------------------------------------------------------
__global__ __launch_bounds__(128) void ff1_kernel(int layer, const float* __restrict__ tau) {
    extern __shared__ float sm[];
    float* Xs  = sm;                     // [128][20]
    float* As  = sm + 128 * 20;          // [128][20]
    float* Ws  = As + 128 * 20;          // [128][132]
    float* red = Ws + 128 * 132;         // [16][8]
    float* rmx = red + 128;              // [16]
    const int tid = threadIdx.x;
    const int r0 = blockIdx.x * 16;
    const int h0 = blockIdx.y * 128;

#pragma unroll
    for (int t = 0; t < 16; t++) {
        int lin = t * 128 + tid;
        int k = lin & 127, m = lin >> 7;
        int gi = (r0 + m) * 128 + k;
        Xs[k * 20 + m] = g_h[gi];
        As[k * 20 + m] = fmaxf(g_pa[gi], g_pb[gi]);
    }
    const float* Wt = g_f1t + layer * 32768;
#pragma unroll
    for (int t = 0; t < 32; t++) {
        int idx = t * 128 + tid;
        int k = idx >> 5, i4 = idx & 31;
        *(float4*)(Ws + k * 132 + i4 * 4) =
            *(const float4*)(Wt + k * 256 + h0 + i4 * 4);
    }
    __syncthreads();
    // rowmax(a)
    {
        int row = tid >> 3, sub = tid & 7;
        float mx = NEGINF;
        for (int k = sub; k < 128; k += 8) mx = fmaxf(mx, As[k * 20 + row]);
        red[row * 8 + sub] = mx;
    }
    __syncthreads();
    if (tid < 16) {
        float mx = red[tid * 8];
#pragma unroll
        for (int s = 1; s < 8; s++) mx = fmaxf(mx, red[tid * 8 + s]);
        rmx[tid] = mx;
    }
    __syncthreads();
    // h = max(h, a - rma); write back (y==0 only, idempotent value)
#pragma unroll
    for (int t = 0; t < 16; t++) {
        int lin = t * 128 + tid;
        int k = lin & 127, m = lin >> 7;
        float v = fmaxf(Xs[k * 20 + m], As[k * 20 + m] - rmx[m]);
        Xs[k * 20 + m] = v;
        if (blockIdx.y == 0) g_h[(r0 + m) * 128 + k] = v;
    }
    __syncthreads();
    // pnorm(h)
    {
        int row = tid >> 3, sub = tid & 7;
        float mx = NEGINF;
        for (int k = sub; k < 128; k += 8) mx = fmaxf(mx, Xs[k * 20 + row]);
        red[row * 8 + sub] = mx;
    }
    __syncthreads();
    if (tid < 16) {
        float mx = red[tid * 8];
#pragma unroll
        for (int s = 1; s < 8; s++) mx = fmaxf(mx, red[tid * 8 + s]);
        rmx[tid] = mx;
    }
    __syncthreads();
#pragma unroll
    for (int t = 0; t < 16; t++) {
        int lin = t * 128 + tid;
        int k = lin & 127, m = lin >> 7;
        Xs[k * 20 + m] -= rmx[m];
    }
    __syncthreads();

    const int ty = tid >> 5, tx = tid & 31;
    float acc[4][4];
#pragma unroll
    for (int m = 0; m < 4; m++)
#pragma unroll
        for (int n = 0; n < 4; n++) acc[m][n] = NEGINF;

#pragma unroll 8
    for (int k = 0; k < 128; k++) {
        float4 xf = *(const float4*)(Xs + k * 20 + ty * 4);
        float4 wf = *(const float4*)(Ws + k * 132 + tx * 4);
        float xv[4] = {xf.x, xf.y, xf.z, xf.w};
        float wv[4] = {wf.x, wf.y, wf.z, wf.w};
#pragma unroll
        for (int m = 0; m < 4; m++)
#pragma unroll
            for (int n = 0; n < 4; n++)
                acc[m][n] = fmaxf(acc[m][n], xv[m] + wv[n]);
    }
    float tv = tau[0];
#pragma unroll
    for (int m = 0; m < 4; m++) {
        int r = r0 + ty * 4 + m;
        float4 v = make_float4(fmaxf(acc[m][0], tv), fmaxf(acc[m][1], tv),
                               fmaxf(acc[m][2], tv), fmaxf(acc[m][3], tv));
        *(float4*)(g_h1 + r * 256 + h0 + tx * 4) = v;
    }
}

// ---------------------------------------------------------------------------
// FF2 GEMM (raw): K=256, BN=64.  grid (98, 2), 128 threads -> g_r.
// ---------------------------------------------------------------------------
__global__ __launch_bounds__(128) void ff2_kernel(int layer) {
    extern __shared__ float sm[];
    float* Xs = sm;            // [256][20]
    float* Ws = sm + 256 * 20; // [256][68]
    const int tid = threadIdx.x;
    const int r0 = blockIdx.x * 16;
    const int h0 = blockIdx.y * 64;

#pragma unroll
    for (int t = 0; t < 32; t++) {
        int lin = t * 128 + tid;
        int k = lin & 255, m = lin >> 8;
        Xs[k * 20 + m] = g_h1[(r0 + m) * 256 + k];
    }
    const float* Wt = g_f2t + layer * 32768;
#pragma unroll
    for (int t = 0; t < 32; t++) {
        int idx = t * 128 + tid;
        int k = idx >> 4, i4 = idx & 15;
        *(float4*)(Ws + k * 68 + i4 * 4) =
            *(const float4*)(Wt + k * 128 + h0 + i4 * 4);
    }
    __syncthreads();

    const int ty = tid >> 4, tx = tid & 15;
    float acc[2][4];
#pragma unroll
    for (int m = 0; m < 2; m++)
#pragma unroll
        for (int n = 0; n < 4; n++) acc[m][n] = NEGINF;

#pragma unroll 8
    for (int k = 0; k < 256; k++) {
        float2 xf = *(const float2*)(Xs + k * 20 + ty * 2);
        float4 wf = *(const float4*)(Ws + k * 68 + tx * 4);
        float xv[2] = {xf.x, xf.y};
        float wv[4] = {wf.x, wf.y, wf.z, wf.w};
#pragma unroll
        for (int m = 0; m < 2; m++)
#pragma unroll
            for (int n = 0; n < 4; n++)
                acc[m][n] = fmaxf(acc[m][n], xv[m] + wv[n]);
    }
#pragma unroll
    for (int m = 0; m < 2; m++) {
        int r = r0 + ty * 2 + m;
        float4 v = make_float4(acc[m][0], acc[m][1], acc[m][2], acc[m][3]);
        *(float4*)(g_r + r * 128 + h0 + tx * 4) = v;
    }
}

// ---------------------------------------------------------------------------
// FF2 combine: rowmax over 128 outs, h = max(h, r - rm).  grid 196, 256 thr.
// One warp per row.
// ---------------------------------------------------------------------------
__global__ void comb2_kernel() {
    const int w = threadIdx.x >> 5, lane = threadIdx.x & 31;
    const int r = blockIdx.x * 8 + w;
    float4 v = *(const float4*)(g_r + r * 128 + lane * 4);
    float m = fmaxf(fmaxf(v.x, v.y), fmaxf(v.z, v.w));
#pragma unroll
    for (int s = 16; s; s >>= 1) m = fmaxf(m, __shfl_xor_sync(0xffffffffu, m, s));
    float4 h = *(float4*)(g_h + r * 128 + lane * 4);
    h.x = fmaxf(h.x, v.x - m);
    h.y = fmaxf(h.y, v.y - m);
    h.z = fmaxf(h.z, v.z - m);
    h.w = fmaxf(h.w, v.w - m);
    *(float4*)(g_h + r * 128 + lane * 4) = h;
}

// ---------------------------------------------------------------------------
// Pool + head.  grid (8, 8), 128 threads.
// ---------------------------------------------------------------------------
__global__ void head_kernel(const float* __restrict__ hW,
                            const float* __restrict__ ls,
                            float* __restrict__ out) {
    __shared__ float pooled[128];
    const int b = blockIdx.x, ct = blockIdx.y, tid = threadIdx.x;

    const float* hp = g_h + (b * 196) * 128 + tid;
    float m0 = NEGINF, m1 = NEGINF, m2 = NEGINF, m3 = NEGINF;
#pragma unroll 4
    for (int n = 0; n < 196; n += 4) {
        m0 = fmaxf(m0, hp[(n + 0) * 128]);
        m1 = fmaxf(m1, hp[(n + 1) * 128]);
        m2 = fmaxf(m2, hp[(n + 2) * 128]);
        m3 = fmaxf(m3, hp[(n + 3) * 128]);
    }
    pooled[tid] = fmaxf(fmaxf(m0, m1), fmaxf(m2, m3));
    __syncthreads();

    int c = ct * 125 + tid;
    if (tid < 125) {
        const float* w = hW + c * 128;
        float a = NEGINF;
#pragma unroll 8
        for (int d = 0; d < 128; d++) a = fmaxf(a, pooled[d] + w[d]);
        out[b * 1000 + c] = a * ls[0];
    }
}

// ---------------------------------------------------------------------------
static const int SMEM_EMBED = (256 * 20 + 256 * 68) * 4;
static const int SMEM_QKV   = (128 * 20 + 128 * 132 + 128 + 16) * 4;
static const int SMEM_FF1   = (128 * 20 * 2 + 128 * 132 + 128 + 16) * 4;
static const int SMEM_FF2   = (256 * 20 + 256 * 68) * 4;

extern "C" void kernel_launch(void* const* d_in, const int* in_sizes, int n_in,
                              void* d_out, int out_size) {
    const float* x   = (const float*)d_in[0];
    const float* eW  = (const float*)d_in[1];
    const float* pos = (const float*)d_in[2];
    const float* qW[2]  = {(const float*)d_in[3],  (const float*)d_in[9]};
    const float* kW[2]  = {(const float*)d_in[4],  (const float*)d_in[10]};
    const float* vW[2]  = {(const float*)d_in[5],  (const float*)d_in[11]};
    const float* f1W[2] = {(const float*)d_in[6],  (const float*)d_in[12]};
    const float* f2W[2] = {(const float*)d_in[7],  (const float*)d_in[13]};
    const float* tau[2] = {(const float*)d_in[8],  (const float*)d_in[14]};
    const float* hW  = (const float*)d_in[15];
    const float* ls  = (const float*)d_in[16];
    float* out = (float*)d_out;

    cudaFuncSetAttribute(embed_kernel, cudaFuncAttributeMaxDynamicSharedMemorySize, SMEM_EMBED);
    cudaFuncSetAttribute(qkv_kernel,   cudaFuncAttributeMaxDynamicSharedMemorySize, SMEM_QKV);
    cudaFuncSetAttribute(ff1_kernel,   cudaFuncAttributeMaxDynamicSharedMemorySize, SMEM_FF1);
    cudaFuncSetAttribute(ff2_kernel,   cudaFuncAttributeMaxDynamicSharedMemorySize, SMEM_FF2);

    wtrans_kernel<<<dim3(32, 11), 256>>>(eW, qW[0], kW[0], vW[0], f1W[0], f2W[0],
                                         qW[1], kW[1], vW[1], f1W[1], f2W[1]);
    embed_kernel<<<dim3(98, 2), 128, SMEM_EMBED>>>(x, pos);
    for (int l = 0; l < 2; l++) {
        qkv_kernel<<<dim3(98, 3), 128, SMEM_QKV>>>(l);
        attnP_kernel<<<dim3(13, 8, 2), 128>>>();
        ff1_kernel<<<dim3(98, 2), 128, SMEM_FF1>>>(l, tau[l]);
        ff2_kernel<<<dim3(98, 2), 128, SMEM_FF2>>>(l);
        comb2_kernel<<<196, 256>>>();
    }
    head_kernel<<<dim3(8, 8), 128>>>(hW, ls, out);
}

// round 5
// speedup vs baseline: 1.7921x; 1.1741x over previous
#include <cuda_runtime.h>

#define NEGINF (-1.0e30f)

// ---------------- persistent scratch ----------------
__device__ float g_h [1568 * 128];
__device__ float g_q [1568 * 128];
__device__ float g_k [1568 * 128];
__device__ float g_v [1568 * 128];
__device__ float g_pa[1568 * 128];
__device__ float g_pb[1568 * 128];
__device__ float g_pc[1568 * 128];
__device__ float g_pd[1568 * 128];
__device__ float g_h1[1568 * 256];
__device__ float g_r [1568 * 128];
__device__ float g_r2[1568 * 128];

// transposed weights [k][i]
__device__ float g_eWt  [256 * 128];
__device__ float g_qkvWt[6 * 128 * 128];
__device__ float g_f1t  [2 * 128 * 256];
__device__ float g_f2t  [2 * 256 * 128];

__device__ __forceinline__ void ma24(float (&a)[2][4], float2 x, float4 w) {
    float xs[2] = {x.x, x.y};
    float ws[4] = {w.x, w.y, w.z, w.w};
#pragma unroll
    for (int m = 0; m < 2; m++)
#pragma unroll
        for (int n = 0; n < 4; n++)
            a[m][n] = fmaxf(a[m][n], xs[m] + ws[n]);
}

__device__ __forceinline__ void ma22(float (&a)[2][2], float2 x, float2 w) {
    a[0][0] = fmaxf(a[0][0], x.x + w.x);
    a[0][1] = fmaxf(a[0][1], x.x + w.y);
    a[1][0] = fmaxf(a[1][0], x.y + w.x);
    a[1][1] = fmaxf(a[1][1], x.y + w.y);
}

// prefetch-pipelined tropical GEMM microkernels (xp/wp pre-offset by thread)
template<int XS, int WS, int K>
__device__ __forceinline__ void tg24(const float* xp, const float* wp,
                                     float (&acc)[2][4]) {
    float2 xa = *(const float2*)xp;
    float4 wa = *(const float4*)wp;
#pragma unroll 8
    for (int k = 0; k < K - 1; k++) {
        float2 xb = *(const float2*)(xp + (k + 1) * XS);
        float4 wb = *(const float4*)(wp + (k + 1) * WS);
        ma24(acc, xa, wa);
        xa = xb; wa = wb;
    }
    ma24(acc, xa, wa);
}

template<int XS, int WS, int K>
__device__ __forceinline__ void tg22(const float* xp, const float* wp,
                                     float (&acc)[2][2]) {
    float2 xa = *(const float2*)xp;
    float2 wa = *(const float2*)wp;
#pragma unroll 8
    for (int k = 0; k < K - 1; k++) {
        float2 xb = *(const float2*)(xp + (k + 1) * XS);
        float2 wb = *(const float2*)(wp + (k + 1) * WS);
        ma22(acc, xa, wa);
        xa = xb; wa = wb;
    }
    ma22(acc, xa, wa);
}

// ---------------------------------------------------------------------------
// Weight transpose: grid (32, 11), 256 threads.
// ---------------------------------------------------------------------------
__global__ void wtrans_kernel(const float* eW,
                              const float* q0, const float* k0, const float* v0,
                              const float* f10, const float* f20,
                              const float* q1, const float* k1, const float* v1,
                              const float* f11, const float* f21) {
    __shared__ float tile[32][33];
    const int id = blockIdx.y;
    const float* src; float* dst; int R, C;
    switch (id) {
        case 0:  src = eW;  dst = g_eWt;               R = 128; C = 256; break;
        case 1:  src = q0;  dst = g_qkvWt + 0 * 16384; R = 128; C = 128; break;
        case 2:  src = k0;  dst = g_qkvWt + 1 * 16384; R = 128; C = 128; break;
        case 3:  src = v0;  dst = g_qkvWt + 2 * 16384; R = 128; C = 128; break;
        case 4:  src = f10; dst = g_f1t;               R = 256; C = 128; break;
        case 5:  src = f20; dst = g_f2t;               R = 128; C = 256; break;
        case 6:  src = q1;  dst = g_qkvWt + 3 * 16384; R = 128; C = 128; break;
        case 7:  src = k1;  dst = g_qkvWt + 4 * 16384; R = 128; C = 128; break;
        case 8:  src = v1;  dst = g_qkvWt + 5 * 16384; R = 128; C = 128; break;
        case 9:  src = f11; dst = g_f1t + 32768;       R = 256; C = 128; break;
        default: src = f21; dst = g_f2t + 32768;       R = 128; C = 256; break;
    }
    const int tilesC = C >> 5;
    const int lin = blockIdx.x;
    if (lin >= tilesC * (R >> 5)) return;
    const int tr = lin / tilesC, tc = lin % tilesC;
    const int x = threadIdx.x & 31, y = threadIdx.x >> 5;
#pragma unroll
    for (int s = 0; s < 4; s++)
        tile[y + s * 8][x] = src[(tr * 32 + y + s * 8) * C + tc * 32 + x];
    __syncthreads();
#pragma unroll
    for (int s = 0; s < 4; s++)
        dst[(tc * 32 + y + s * 8) * R + tr * 32 + x] = tile[x][y + s * 8];
}

// ---------------------------------------------------------------------------
// Embed: patchify + tropical GEMM (K=256) + pos.  grid (98, 2), 128 threads.
// ---------------------------------------------------------------------------
__global__ __launch_bounds__(128) void embed_kernel(const float* __restrict__ x,
                                                    const float* __restrict__ pos) {
    extern __shared__ float sm[];
    float* Xs = sm;            // [256][20]
    float* Ws = sm + 256 * 20; // [256][68]
    const int tid = threadIdx.x;
    const int r0 = blockIdx.x * 16;
    const int h0 = blockIdx.y * 64;

#pragma unroll
    for (int t = 0; t < 32; t++) {
        int lin = t * 128 + tid;
        int px = lin & 15, m = (lin >> 4) & 15, py = lin >> 8;
        int r = r0 + m;
        int b = r / 196, n = r % 196;
        int gy = n / 14, gx = n % 14;
        Xs[(py * 16 + px) * 20 + m] =
            x[(b * 224 + gy * 16 + py) * 224 + gx * 16 + px];
    }
#pragma unroll
    for (int t = 0; t < 32; t++) {
        int idx = t * 128 + tid;
        int k = idx >> 4, i4 = idx & 15;
        *(float4*)(Ws + k * 68 + i4 * 4) =
            *(const float4*)(g_eWt + k * 128 + h0 + i4 * 4);
    }
    __syncthreads();

    const int ty = tid >> 4, tx = tid & 15;
    float acc[2][4];
#pragma unroll
    for (int m = 0; m < 2; m++)
#pragma unroll
        for (int n = 0; n < 4; n++) acc[m][n] = NEGINF;

    tg24<20, 68, 256>(Xs + ty * 2, Ws + tx * 4, acc);

#pragma unroll
    for (int m = 0; m < 2; m++) {
        int r = r0 + ty * 2 + m;
        int nn = r % 196;
#pragma unroll
        for (int n = 0; n < 4; n++) {
            int col = h0 + tx * 4 + n;
            g_h[r * 128 + col] = acc[m][n] + pos[nn * 128 + col];
        }
    }
}

// ---------------------------------------------------------------------------
// QKV: rowmax(h) + GEMM on raw h, rmax subtracted in epilogue.
// BM=16, BN=128, 256 threads (2x4 tiles), grid (98, 3).
// ---------------------------------------------------------------------------
__global__ __launch_bounds__(256) void qkv_kernel(int layer) {
    extern __shared__ float sm[];
    float* Xs  = sm;                 // [128][20]
    float* Ws  = sm + 128 * 20;      // [128][132]
    float* red = Ws + 128 * 132;     // [16][16]
    float* rmx = red + 256;          // [16]
    const int tid = threadIdx.x;
    const int r0 = blockIdx.x * 16;
    const int which = blockIdx.y;

#pragma unroll
    for (int t = 0; t < 8; t++) {
        int lin = t * 256 + tid;
        int k = lin & 127, m = lin >> 7;
        Xs[k * 20 + m] = g_h[(r0 + m) * 128 + k];
    }
    const float* Wt = g_qkvWt + (layer * 3 + which) * 16384;
#pragma unroll
    for (int t = 0; t < 16; t++) {
        int idx = t * 256 + tid;
        int k = idx >> 5, i4 = idx & 31;
        *(float4*)(Ws + k * 132 + i4 * 4) =
            *(const float4*)(Wt + k * 128 + i4 * 4);
    }
    __syncthreads();
    {
        int row = tid >> 4, sub = tid & 15;
        float mx = NEGINF;
#pragma unroll
        for (int k = sub; k < 128; k += 16) mx = fmaxf(mx, Xs[k * 20 + row]);
        red[row * 16 + sub] = mx;
    }
    __syncthreads();
    if (tid < 16) {
        float mx = red[tid * 16];
#pragma unroll
        for (int s = 1; s < 16; s++) mx = fmaxf(mx, red[tid * 16 + s]);
        rmx[tid] = mx;
    }
    __syncthreads();

    const int ty = tid >> 5, tx = tid & 31;
    float acc[2][4];
#pragma unroll
    for (int m = 0; m < 2; m++)
#pragma unroll
        for (int n = 0; n < 4; n++) acc[m][n] = NEGINF;

    tg24<20, 132, 128>(Xs + ty * 2, Ws + tx * 4, acc);

    float* O = (which == 0) ? g_q : ((which == 1) ? g_k : g_v);
#pragma unroll
    for (int m = 0; m < 2; m++) {
        int row = ty * 2 + m;
        float rm = rmx[row];
        *(float4*)(O + (r0 + row) * 128 + tx * 4) =
            make_float4(acc[m][0] - rm, acc[m][1] - rm,
                        acc[m][2] - rm, acc[m][3] - rm);
    }
}

// ---------------------------------------------------------------------------
// Attention partial.  grid (13, 8, 4): 16 q-rows, batch, j-quarter.
// j-chunks: j0 = z*32, stride 128.  Prefetch-pipelined S and O loops.
// ---------------------------------------------------------------------------
__global__ __launch_bounds__(128) void attnP_kernel() {
    __shared__ float Qs[128 * 20];
    __shared__ float Ks[128 * 34];
    __shared__ float Vs[32 * 132];
    __shared__ float Ss[32 * 18];
    const int tid = threadIdx.x;
    const int b = blockIdx.y;
    const int i0 = blockIdx.x * 16;
    const int z = blockIdx.z;
    const int ty = tid >> 4, tx = tid & 15;

#pragma unroll
    for (int t = 0; t < 16; t++) {
        int lin = t * 128 + tid;
        int d = lin & 127, i = lin >> 7;
        Qs[d * 20 + i] = (i0 + i < 196) ? g_q[(b * 196 + i0 + i) * 128 + d] : NEGINF;
    }

    float o0[8], o1[8];
#pragma unroll
    for (int n = 0; n < 8; n++) { o0[n] = NEGINF; o1[n] = NEGINF; }

    for (int j0 = z * 32; j0 < 196; j0 += 128) {
        __syncthreads();
#pragma unroll
        for (int t = 0; t < 32; t++) {
            int lin = t * 128 + tid;
            int d = lin & 127, j = lin >> 7;
            bool ok = (j0 + j) < 196;
            int r = b * 196 + j0 + j;
            Ks[d * 34 + j] = ok ? g_k[r * 128 + d] : NEGINF;
            Vs[j * 132 + d] = ok ? g_v[r * 128 + d] : NEGINF;
        }
        __syncthreads();

        // S = max_d (Q + K): 16x32 tile, 2x2/thread, prefetched
        float s00 = NEGINF, s01 = NEGINF, s10 = NEGINF, s11 = NEGINF;
        {
            float2 qa = *(const float2*)(Qs + ty * 2);
            float2 ka = *(const float2*)(Ks + tx * 2);
#pragma unroll 8
            for (int d = 0; d < 127; d++) {
                float2 qb = *(const float2*)(Qs + (d + 1) * 20 + ty * 2);
                float2 kb = *(const float2*)(Ks + (d + 1) * 34 + tx * 2);
                s00 = fmaxf(s00, qa.x + ka.x);
                s01 = fmaxf(s01, qa.x + ka.y);
                s10 = fmaxf(s10, qa.y + ka.x);
                s11 = fmaxf(s11, qa.y + ka.y);
                qa = qb; ka = kb;
            }
            s00 = fmaxf(s00, qa.x + ka.x);
            s01 = fmaxf(s01, qa.x + ka.y);
            s10 = fmaxf(s10, qa.y + ka.x);
            s11 = fmaxf(s11, qa.y + ka.y);
        }
        Ss[(tx * 2 + 0) * 18 + ty * 2 + 0] = s00;
        Ss[(tx * 2 + 1) * 18 + ty * 2 + 0] = s01;
        Ss[(tx * 2 + 0) * 18 + ty * 2 + 1] = s10;
        Ss[(tx * 2 + 1) * 18 + ty * 2 + 1] = s11;
        __syncthreads();

        // O update: 16x128 tile, 2x8/thread, prefetched
        {
            float2 sa = *(const float2*)(Ss + ty * 2);
            float4 va = *(const float4*)(Vs + tx * 8);
            float4 vb = *(const float4*)(Vs + tx * 8 + 4);
#pragma unroll 4
            for (int j = 0; j < 31; j++) {
                float2 sn = *(const float2*)(Ss + (j + 1) * 18 + ty * 2);
                float4 vc = *(const float4*)(Vs + (j + 1) * 132 + tx * 8);
                float4 vd = *(const float4*)(Vs + (j + 1) * 132 + tx * 8 + 4);
                float vv[8] = {va.x, va.y, va.z, va.w, vb.x, vb.y, vb.z, vb.w};
#pragma unroll
                for (int n = 0; n < 8; n++) {
                    o0[n] = fmaxf(o0[n], sa.x + vv[n]);
                    o1[n] = fmaxf(o1[n], sa.y + vv[n]);
                }
                sa = sn; va = vc; vb = vd;
            }
            float vv[8] = {va.x, va.y, va.z, va.w, vb.x, vb.y, vb.z, vb.w};
#pragma unroll
            for (int n = 0; n < 8; n++) {
                o0[n] = fmaxf(o0[n], sa.x + vv[n]);
                o1[n] = fmaxf(o1[n], sa.y + vv[n]);
            }
        }
    }

    float* P = (z == 0) ? g_pa : ((z == 1) ? g_pb : ((z == 2) ? g_pc : g_pd));
    int i_a = ty * 2, i_b = ty * 2 + 1;
    if (i0 + i_a < 196) {
        int base = (b * 196 + i0 + i_a) * 128 + tx * 8;
        *(float4*)(P + base)     = make_float4(o0[0], o0[1], o0[2], o0[3]);
        *(float4*)(P + base + 4) = make_float4(o0[4], o0[5], o0[6], o0[7]);
    }
    if (i0 + i_b < 196) {
        int base = (b * 196 + i0 + i_b) * 128 + tx * 8;
        *(float4*)(P + base)     = make_float4(o1[0], o1[1], o1[2], o1[3]);
        *(float4*)(P + base + 4) = make_float4(o1[4], o1[5], o1[6], o1[7]);
    }
}

// ---------------------------------------------------------------------------
// FF1: combine 4 attn partials + residual + pnorm (epilogue) + GEMM + tau.
// BM=16, BN=128, 256 threads (2x4 tiles), grid (98, 2).
// ---------------------------------------------------------------------------
__global__ __launch_bounds__(256) void ff1_kernel(int layer, const float* __restrict__ tau) {
    extern __shared__ float sm[];
    float* Xs  = sm;                     // [128][20]
    float* As  = sm + 2560;              // [128][20]
    float* Ws  = As + 2560;              // [128][132]
    float* red = Ws + 16896;             // [16][16]
    float* rmx = red + 256;              // [16]
    const int tid = threadIdx.x;
    const int r0 = blockIdx.x * 16;
    const int h0 = blockIdx.y * 128;

#pragma unroll
    for (int t = 0; t < 8; t++) {
        int lin = t * 256 + tid;
        int k = lin & 127, m = lin >> 7;
        int gi = (r0 + m) * 128 + k;
        Xs[k * 20 + m] = g_h[gi];
        As[k * 20 + m] = fmaxf(fmaxf(g_pa[gi], g_pb[gi]),
                               fmaxf(g_pc[gi], g_pd[gi]));
    }
    const float* Wt = g_f1t + layer * 32768;
#pragma unroll
    for (int t = 0; t < 16; t++) {
        int idx = t * 256 + tid;
        int k = idx >> 5, i4 = idx & 31;
        *(float4*)(Ws + k * 132 + i4 * 4) =
            *(const float4*)(Wt + k * 256 + h0 + i4 * 4);
    }
    __syncthreads();
    // rowmax(a)
    {
        int row = tid >> 4, sub = tid & 15;
        float mx = NEGINF;
#pragma unroll
        for (int k = sub; k < 128; k += 16) mx = fmaxf(mx, As[k * 20 + row]);
        red[row * 16 + sub] = mx;
    }
    __syncthreads();
    if (tid < 16) {
        float mx = red[tid * 16];
#pragma unroll
        for (int s = 1; s < 16; s++) mx = fmaxf(mx, red[tid * 16 + s]);
        rmx[tid] = mx;
    }
    __syncthreads();
    // h' = max(h, a - rma); write back once
#pragma unroll
    for (int t = 0; t < 8; t++) {
        int lin = t * 256 + tid;
        int k = lin & 127, m = lin >> 7;
        float v = fmaxf(Xs[k * 20 + m], As[k * 20 + m] - rmx[m]);
        Xs[k * 20 + m] = v;
        if (blockIdx.y == 0) g_h[(r0 + m) * 128 + k] = v;
    }
    __syncthreads();
    // rowmax(h') for epilogue subtraction
    {
        int row = tid >> 4, sub = tid & 15;
        float mx = NEGINF;
#pragma unroll
        for (int k = sub; k < 128; k += 16) mx = fmaxf(mx, Xs[k * 20 + row]);
        red[row * 16 + sub] = mx;
    }
    __syncthreads();
    if (tid < 16) {
        float mx = red[tid * 16];
#pragma unroll
        for (int s = 1; s < 16; s++) mx = fmaxf(mx, red[tid * 16 + s]);
        rmx[tid] = mx;
    }
    __syncthreads();

    const int ty = tid >> 5, tx = tid & 31;
    float acc[2][4];
#pragma unroll
    for (int m = 0; m < 2; m++)
#pragma unroll
        for (int n = 0; n < 4; n++) acc[m][n] = NEGINF;

    tg24<20, 132, 128>(Xs + ty * 2, Ws + tx * 4, acc);

    const float tv = tau[0];
#pragma unroll
    for (int m = 0; m < 2; m++) {
        int row = ty * 2 + m;
        float rm = rmx[row];
        *(float4*)(g_h1 + (r0 + row) * 256 + h0 + tx * 4) =
            make_float4(fmaxf(acc[m][0] - rm, tv), fmaxf(acc[m][1] - rm, tv),
                        fmaxf(acc[m][2] - rm, tv), fmaxf(acc[m][3] - rm, tv));
    }
}

// ---------------------------------------------------------------------------
// FF2 GEMM (raw, K-split 2): BM=16, BN=64, K=128 per CTA, 256 threads (2x2).
// grid (98, 2, 2): y = n-half, z = k-half -> g_r / g_r2.
// ---------------------------------------------------------------------------
__global__ __launch_bounds__(256) void ff2_kernel(int layer) {
    extern __shared__ float sm[];
    float* Xs = sm;            // [128][20]
    float* Ws = sm + 2560;     // [128][68]
    const int tid = threadIdx.x;
    const int r0 = blockIdx.x * 16;
    const int h0 = blockIdx.y * 64;
    const int k0 = blockIdx.z * 128;

#pragma unroll
    for (int t = 0; t < 8; t++) {
        int lin = t * 256 + tid;
        int k = lin & 127, m = lin >> 7;
        Xs[k * 20 + m] = g_h1[(r0 + m) * 256 + k0 + k];
    }
    const float* Wt = g_f2t + layer * 32768;
#pragma unroll
    for (int t = 0; t < 8; t++) {
        int idx = t * 256 + tid;
        int k = idx >> 4, i4 = idx & 15;
        *(float4*)(Ws + k * 68 + i4 * 4) =
            *(const float4*)(Wt + (k0 + k) * 128 + h0 + i4 * 4);
    }
    __syncthreads();

    const int ty = tid >> 5, tx = tid & 31;
    float acc[2][2];
    acc[0][0] = acc[0][1] = acc[1][0] = acc[1][1] = NEGINF;

    tg22<20, 68, 128>(Xs + ty * 2, Ws + tx * 2, acc);

    float* O = blockIdx.z ? g_r2 : g_r;
#pragma unroll
    for (int m = 0; m < 2; m++) {
        int r = r0 + ty * 2 + m;
        *(float2*)(O + r * 128 + h0 + tx * 2) = make_float2(acc[m][0], acc[m][1]);
    }
}

// ---------------------------------------------------------------------------
// FF2 combine: out = max(r, r2); rowmax; h = max(h, out - rm). grid 196, 256.
// ---------------------------------------------------------------------------
__global__ void comb2_kernel() {
    const int w = threadIdx.x >> 5, lane = threadIdx.x & 31;
    const int r = blockIdx.x * 8 + w;
    float4 a = *(const float4*)(g_r  + r * 128 + lane * 4);
    float4 c = *(const float4*)(g_r2 + r * 128 + lane * 4);
    float4 v = make_float4(fmaxf(a.x, c.x), fmaxf(a.y, c.y),
                           fmaxf(a.z, c.z), fmaxf(a.w, c.w));
    float m = fmaxf(fmaxf(v.x, v.y), fmaxf(v.z, v.w));
#pragma unroll
    for (int s = 16; s; s >>= 1) m = fmaxf(m, __shfl_xor_sync(0xffffffffu, m, s));
    float4 h = *(float4*)(g_h + r * 128 + lane * 4);
    h.x = fmaxf(h.x, v.x - m);
    h.y = fmaxf(h.y, v.y - m);
    h.z = fmaxf(h.z, v.z - m);
    h.w = fmaxf(h.w, v.w - m);
    *(float4*)(g_h + r * 128 + lane * 4) = h;
}

// ---------------------------------------------------------------------------
// Pool + head.  grid (8, 8), 128 threads.
// ---------------------------------------------------------------------------
__global__ void head_kernel(const float* __restrict__ hW,
                            const float* __restrict__ ls,
                            float* __restrict__ out) {
    __shared__ float pooled[128];
    const int b = blockIdx.x, ct = blockIdx.y, tid = threadIdx.x;

    const float* hp = g_h + (b * 196) * 128 + tid;
    float m0 = NEGINF, m1 = NEGINF, m2 = NEGINF, m3 = NEGINF;
#pragma unroll 4
    for (int n = 0; n < 196; n += 4) {
        m0 = fmaxf(m0, hp[(n + 0) * 128]);
        m1 = fmaxf(m1, hp[(n + 1) * 128]);
        m2 = fmaxf(m2, hp[(n + 2) * 128]);
        m3 = fmaxf(m3, hp[(n + 3) * 128]);
    }
    pooled[tid] = fmaxf(fmaxf(m0, m1), fmaxf(m2, m3));
    __syncthreads();

    int c = ct * 125 + tid;
    if (tid < 125) {
        const float* w = hW + c * 128;
        float a = NEGINF;
#pragma unroll 8
        for (int d = 0; d < 128; d++) a = fmaxf(a, pooled[d] + w[d]);
        out[b * 1000 + c] = a * ls[0];
    }
}

// ---------------------------------------------------------------------------
static const int SMEM_EMBED = (256 * 20 + 256 * 68) * 4;
static const int SMEM_QKV   = (128 * 20 + 128 * 132 + 256 + 16) * 4;
static const int SMEM_FF1   = (128 * 20 * 2 + 128 * 132 + 256 + 16) * 4;
static const int SMEM_FF2   = (128 * 20 + 128 * 68) * 4;

extern "C" void kernel_launch(void* const* d_in, const int* in_sizes, int n_in,
                              void* d_out, int out_size) {
    const float* x   = (const float*)d_in[0];
    const float* eW  = (const float*)d_in[1];
    const float* pos = (const float*)d_in[2];
    const float* qW[2]  = {(const float*)d_in[3],  (const float*)d_in[9]};
    const float* kW[2]  = {(const float*)d_in[4],  (const float*)d_in[10]};
    const float* vW[2]  = {(const float*)d_in[5],  (const float*)d_in[11]};
    const float* f1W[2] = {(const float*)d_in[6],  (const float*)d_in[12]};
    const float* f2W[2] = {(const float*)d_in[7],  (const float*)d_in[13]};
    const float* tau[2] = {(const float*)d_in[8],  (const float*)d_in[14]};
    const float* hW  = (const float*)d_in[15];
    const float* ls  = (const float*)d_in[16];
    float* out = (float*)d_out;

    cudaFuncSetAttribute(embed_kernel, cudaFuncAttributeMaxDynamicSharedMemorySize, SMEM_EMBED);
    cudaFuncSetAttribute(qkv_kernel,   cudaFuncAttributeMaxDynamicSharedMemorySize, SMEM_QKV);
    cudaFuncSetAttribute(ff1_kernel,   cudaFuncAttributeMaxDynamicSharedMemorySize, SMEM_FF1);
    cudaFuncSetAttribute(ff2_kernel,   cudaFuncAttributeMaxDynamicSharedMemorySize, SMEM_FF2);

    wtrans_kernel<<<dim3(32, 11), 256>>>(eW, qW[0], kW[0], vW[0], f1W[0], f2W[0],
                                         qW[1], kW[1], vW[1], f1W[1], f2W[1]);
    embed_kernel<<<dim3(98, 2), 128, SMEM_EMBED>>>(x, pos);
    for (int l = 0; l < 2; l++) {
        qkv_kernel<<<dim3(98, 3), 256, SMEM_QKV>>>(l);
        attnP_kernel<<<dim3(13, 8, 4), 128>>>();
        ff1_kernel<<<dim3(98, 2), 256, SMEM_FF1>>>(l, tau[l]);
        ff2_kernel<<<dim3(98, 2, 2), 256, SMEM_FF2>>>(l);
        comb2_kernel<<<196, 256>>>();
    }
    head_kernel<<<dim3(8, 8), 128>>>(hW, ls, out);
}